// round 2
// baseline (speedup 1.0000x reference)
#include <cuda_runtime.h>

#define NN 100000
#define EE 3200000
#define EA 3300000     // EE + NN self loops
#define HH 32
#define MM 64
#define CC 10
#define GG 64

// ---------------- scratch (device globals; no allocation allowed) ----------
__device__ int   g_count[NN];
__device__ int   g_cursor[NN];
__device__ int   g_rowptr[NN + 1];
__device__ float g_deg[NN];           // degree, then dinv in-place
__device__ int2  g_cv[EA];            // per-edge: (src, norm bits), CSR by dst
__device__ float g_bufA[NN * HH];     // h @ W
__device__ float g_bufB[NN * HH];     // aggregated output
__device__ float g_pool[GG * HH];
__device__ int   g_cnt[GG];

// ---------------- init -----------------------------------------------------
__global__ void k_zero() {
    int i = blockIdx.x * blockDim.x + threadIdx.x;
    if (i < NN) { g_count[i] = 0; g_deg[i] = 0.f; }
    if (i < GG * HH) g_pool[i] = 0.f;
    if (i < GG) g_cnt[i] = 0;
}

// ---------------- CSR build -------------------------------------------------
__global__ void k_hist(const int* __restrict__ ei,
                       const float* __restrict__ ew) {
    int e = blockIdx.x * blockDim.x + threadIdx.x;
    if (e >= EA) return;
    int dst; float w;
    if (e < EE) { dst = ei[EE + e]; w = ew[e]; }
    else        { dst = e - EE;     w = 1.f;   }
    atomicAdd(&g_count[dst], 1);
    atomicAdd(&g_deg[dst], w);
}

__global__ void k_dinv() {
    int i = blockIdx.x * blockDim.x + threadIdx.x;
    if (i >= NN) return;
    float d = g_deg[i];
    g_deg[i] = (d > 0.f) ? rsqrtf(fmaxf(d, 1e-30f)) : 0.f;
}

// single-block scan over g_count -> g_rowptr (exclusive) + g_cursor copy
__global__ void k_scan() {
    __shared__ int wt[32];
    __shared__ int s_carry;
    int tid = threadIdx.x;   // 1024 threads
    if (tid == 0) s_carry = 0;
    __syncthreads();
    for (int base = 0; base < NN; base += 1024) {
        int i = base + tid;
        int v = (i < NN) ? g_count[i] : 0;
        int x = v;
        #pragma unroll
        for (int d = 1; d < 32; d <<= 1) {
            int y = __shfl_up_sync(0xffffffffu, x, d);
            if ((tid & 31) >= d) x += y;
        }
        if ((tid & 31) == 31) wt[tid >> 5] = x;
        __syncthreads();
        if (tid < 32) {
            int t = wt[tid];
            int xx = t;
            #pragma unroll
            for (int d = 1; d < 32; d <<= 1) {
                int y = __shfl_up_sync(0xffffffffu, xx, d);
                if (tid >= d) xx += y;
            }
            wt[tid] = xx - t;   // exclusive warp offsets
        }
        __syncthreads();
        int incl = x + wt[tid >> 5];
        int excl = incl - v;
        int out = s_carry + excl;
        if (i < NN) { g_rowptr[i] = out; g_cursor[i] = out; }
        __syncthreads();
        if (tid == 1023) s_carry += incl;
        __syncthreads();
    }
    if (tid == 0) g_rowptr[NN] = s_carry;
}

__global__ void k_scatter(const int* __restrict__ ei,
                          const float* __restrict__ ew) {
    int e = blockIdx.x * blockDim.x + threadIdx.x;
    if (e >= EA) return;
    int src, dst; float w;
    if (e < EE) { src = ei[e]; dst = ei[EE + e]; w = ew[e]; }
    else        { src = dst = e - EE;            w = 1.f;   }
    float nv = g_deg[src] * w * g_deg[dst];
    int idx = atomicAdd(&g_cursor[dst], 1);
    g_cv[idx] = make_int2(src, __float_as_int(nv));
}

// ---------------- GEMMs -----------------------------------------------------
// g_bufA[N,32] = X[N,128] @ W[128,32]
__global__ void __launch_bounds__(256) k_gemm128(const float* __restrict__ X,
                                                 const float* __restrict__ W) {
    __shared__ float4 sW[128 * 8];   // W as [k][o/4]
    __shared__ float  sX[256 * 17];  // 16-wide k-chunk, pad 17
    int tid = threadIdx.x;
    for (int i = tid; i < 1024; i += 256) sW[i] = ((const float4*)W)[i];
    float acc[32];
    #pragma unroll
    for (int o = 0; o < 32; o++) acc[o] = 0.f;
    int row = blockIdx.x * 256 + tid;
    for (int kc = 0; kc < 8; kc++) {
        __syncthreads();
        for (int i = tid; i < 256 * 16; i += 256) {
            int r = i >> 4, c = i & 15;
            int rr = blockIdx.x * 256 + r;
            sX[r * 17 + c] = (rr < NN) ? X[rr * 128 + kc * 16 + c] : 0.f;
        }
        __syncthreads();
        #pragma unroll
        for (int kk = 0; kk < 16; kk++) {
            float xv = sX[tid * 17 + kk];
            int k = kc * 16 + kk;
            #pragma unroll
            for (int o4 = 0; o4 < 8; o4++) {
                float4 wv = sW[k * 8 + o4];
                acc[o4 * 4 + 0] += xv * wv.x;
                acc[o4 * 4 + 1] += xv * wv.y;
                acc[o4 * 4 + 2] += xv * wv.z;
                acc[o4 * 4 + 3] += xv * wv.w;
            }
        }
    }
    if (row < NN) {
        float4* Y4 = (float4*)g_bufA;
        #pragma unroll
        for (int j = 0; j < 8; j++)
            Y4[row * 8 + j] = make_float4(acc[4*j], acc[4*j+1], acc[4*j+2], acc[4*j+3]);
    }
}

// g_bufA[N,32] = g_bufB[N,32] @ W[32,32]
__global__ void __launch_bounds__(256) k_gemm32(const float* __restrict__ W) {
    __shared__ float4 sW[32 * 8];
    __shared__ float  sX[256 * 33];
    int tid = threadIdx.x;
    for (int i = tid; i < 256; i += 256) sW[i] = ((const float4*)W)[i];
    for (int i = tid; i < 256 * 32; i += 256) {
        int r = i >> 5, c = i & 31;
        int rr = blockIdx.x * 256 + r;
        sX[r * 33 + c] = (rr < NN) ? g_bufB[rr * 32 + c] : 0.f;
    }
    __syncthreads();
    float acc[32];
    #pragma unroll
    for (int o = 0; o < 32; o++) acc[o] = 0.f;
    #pragma unroll
    for (int kk = 0; kk < 32; kk++) {
        float xv = sX[tid * 33 + kk];
        #pragma unroll
        for (int o4 = 0; o4 < 8; o4++) {
            float4 wv = sW[kk * 8 + o4];
            acc[o4 * 4 + 0] += xv * wv.x;
            acc[o4 * 4 + 1] += xv * wv.y;
            acc[o4 * 4 + 2] += xv * wv.z;
            acc[o4 * 4 + 3] += xv * wv.w;
        }
    }
    int row = blockIdx.x * 256 + tid;
    if (row < NN) {
        float4* Y4 = (float4*)g_bufA;
        #pragma unroll
        for (int j = 0; j < 8; j++)
            Y4[row * 8 + j] = make_float4(acc[4*j], acc[4*j+1], acc[4*j+2], acc[4*j+3]);
    }
}

// ---------------- edge aggregation (gather, warp per node) ------------------
__global__ void __launch_bounds__(256) k_agg(const float* __restrict__ bias, int relu) {
    int w = (blockIdx.x * blockDim.x + threadIdx.x) >> 5;
    int lane = threadIdx.x & 31;
    if (w >= NN) return;
    int beg = g_rowptr[w], end = g_rowptr[w + 1];
    float acc = 0.f;
    #pragma unroll 4
    for (int e = beg; e < end; e++) {
        int2 cv = __ldg(&g_cv[e]);
        acc += __int_as_float(cv.y) * __ldg(&g_bufA[cv.x * 32 + lane]);
    }
    acc += bias[lane];
    if (relu) acc = fmaxf(acc, 0.f);
    g_bufB[w * 32 + lane] = acc;
}

// ---------------- mean pool -------------------------------------------------
__global__ void k_pool(const int* __restrict__ batch) {
    int i = blockIdx.x * blockDim.x + threadIdx.x;
    if (i >= NN * 32) return;
    int n = i >> 5, f = i & 31;
    int b = batch[n];
    atomicAdd(&g_pool[b * 32 + f], g_bufB[i]);
    if (f == 0) atomicAdd(&g_cnt[b], 1);
}

// ---------------- MLP head (single block) -----------------------------------
__global__ void k_mlp(const float* __restrict__ L1w, const float* __restrict__ L1b,
                      const float* __restrict__ L2w, const float* __restrict__ L2b,
                      const float* __restrict__ L3w, const float* __restrict__ L3b,
                      const float* __restrict__ L4w, const float* __restrict__ L4b,
                      float* __restrict__ out) {
    __shared__ float A[GG * MM];
    __shared__ float B[GG * MM];
    int tid = threadIdx.x;  // 256
    for (int i = tid; i < GG * HH; i += 256) {
        int g = i >> 5, f = i & 31;
        float c = (float)g_cnt[g];
        if (c < 1.f) c = 1.f;
        A[g * MM + f] = g_pool[i] / c;
    }
    __syncthreads();
    // L1: 32 -> 64, relu
    for (int i = tid; i < GG * MM; i += 256) {
        int g = i >> 6, m = i & 63;
        float a = L1b[m];
        #pragma unroll
        for (int k = 0; k < HH; k++) a += A[g * MM + k] * L1w[k * MM + m];
        B[g * MM + m] = fmaxf(a, 0.f);
    }
    __syncthreads();
    // L2: 64 -> 64, relu
    for (int i = tid; i < GG * MM; i += 256) {
        int g = i >> 6, m = i & 63;
        float a = L2b[m];
        #pragma unroll
        for (int k = 0; k < MM; k++) a += B[g * MM + k] * L2w[k * MM + m];
        A[g * MM + m] = fmaxf(a, 0.f);
    }
    __syncthreads();
    // L3: 64 -> 64, relu
    for (int i = tid; i < GG * MM; i += 256) {
        int g = i >> 6, m = i & 63;
        float a = L3b[m];
        #pragma unroll
        for (int k = 0; k < MM; k++) a += A[g * MM + k] * L3w[k * MM + m];
        B[g * MM + m] = fmaxf(a, 0.f);
    }
    __syncthreads();
    // L4: 64 -> 10
    for (int i = tid; i < GG * CC; i += 256) {
        int g = i / CC, c = i - g * CC;
        float a = L4b[c];
        #pragma unroll
        for (int k = 0; k < MM; k++) a += B[g * MM + k] * L4w[k * CC + c];
        out[i] = a;
    }
}

// ---------------- launch -----------------------------------------------------
extern "C" void kernel_launch(void* const* d_in, const int* in_sizes, int n_in,
                              void* d_out, int out_size) {
    const float* x    = (const float*)d_in[0];
    const float* ew   = (const float*)d_in[1];
    const float* W1   = (const float*)d_in[2];
    const float* b1   = (const float*)d_in[3];
    const float* W2   = (const float*)d_in[4];
    const float* b2   = (const float*)d_in[5];
    const float* W3   = (const float*)d_in[6];
    const float* b3   = (const float*)d_in[7];
    const float* L1w  = (const float*)d_in[8];
    const float* L1b  = (const float*)d_in[9];
    const float* L2w  = (const float*)d_in[10];
    const float* L2b  = (const float*)d_in[11];
    const float* L3w  = (const float*)d_in[12];
    const float* L3b  = (const float*)d_in[13];
    const float* L4w  = (const float*)d_in[14];
    const float* L4b  = (const float*)d_in[15];
    const int*   ei   = (const int*)d_in[16];   // int32 (JAX x64 disabled)
    const int*   bat  = (const int*)d_in[17];   // int32
    float* out = (float*)d_out;

    const int nb_node  = (NN + 255) / 256;          // 391
    const int nb_edge  = (EA + 255) / 256;          // 12891
    const int nb_nwarp = (NN * 32 + 255) / 256;     // 12500

    k_zero<<<nb_node, 256>>>();
    k_hist<<<nb_edge, 256>>>(ei, ew);
    k_dinv<<<nb_node, 256>>>();
    k_scan<<<1, 1024>>>();
    k_scatter<<<nb_edge, 256>>>(ei, ew);

    // conv1
    k_gemm128<<<nb_node, 256>>>(x, W1);
    k_agg<<<nb_nwarp, 256>>>(b1, 1);
    // conv2
    k_gemm32<<<nb_node, 256>>>(W2);
    k_agg<<<nb_nwarp, 256>>>(b2, 1);
    // conv3
    k_gemm32<<<nb_node, 256>>>(W3);
    k_agg<<<nb_nwarp, 256>>>(b3, 0);

    k_pool<<<nb_nwarp, 256>>>(bat);
    k_mlp<<<1, 256>>>(L1w, L1b, L2w, L2b, L3w, L3b, L4w, L4b, out);
}

// round 3
// speedup vs baseline: 1.1477x; 1.1477x over previous
#include <cuda_runtime.h>

#define NN 100000
#define EE 3200000
#define EA 3300000     // EE + NN self loops
#define HH 32
#define MM 64
#define CC 10
#define GG 64
#define NB 98          // ceil(NN / 1024) scan blocks

// ---------------- scratch (device globals; no allocation allowed) ----------
__device__ int   g_count[NN];
__device__ int   g_cursor[NN];
__device__ int   g_rowptr[NN + 1];
__device__ float g_deg[NN];           // degree, then dinv in-place
__device__ int   g_blocksum[NB];
__device__ int   g_blockoff[NB];
__device__ int2  g_cv[EA];            // per-edge: (src, norm bits), CSR by dst
__device__ float g_bufA[NN * HH];     // h @ W
__device__ float g_bufB[NN * HH];     // aggregated output
__device__ float g_pool[GG * HH];
__device__ int   g_cnt[GG];

// ---------------- init -----------------------------------------------------
__global__ void k_zero() {
    int i = blockIdx.x * blockDim.x + threadIdx.x;
    if (i < NN) { g_count[i] = 0; g_deg[i] = 0.f; }
    if (i < GG * HH) g_pool[i] = 0.f;
    if (i < GG) g_cnt[i] = 0;
}

// ---------------- CSR build -------------------------------------------------
__global__ void k_hist(const int* __restrict__ ei,
                       const float* __restrict__ ew) {
    int e = blockIdx.x * blockDim.x + threadIdx.x;
    if (e >= EA) return;
    int dst; float w;
    if (e < EE) { dst = ei[EE + e]; w = ew[e]; }
    else        { dst = e - EE;     w = 1.f;   }
    atomicAdd(&g_count[dst], 1);
    atomicAdd(&g_deg[dst], w);
}

// phase A: block-local exclusive scan of g_count; also fused deg -> dinv
__global__ void __launch_bounds__(1024) k_scanA() {
    __shared__ int wt[32];
    int tid = threadIdx.x;
    int i = blockIdx.x * 1024 + tid;
    int v = (i < NN) ? g_count[i] : 0;
    int x = v;
    #pragma unroll
    for (int d = 1; d < 32; d <<= 1) {
        int y = __shfl_up_sync(0xffffffffu, x, d);
        if ((tid & 31) >= d) x += y;
    }
    if ((tid & 31) == 31) wt[tid >> 5] = x;
    __syncthreads();
    if (tid < 32) {
        int t = wt[tid];
        int xx = t;
        #pragma unroll
        for (int d = 1; d < 32; d <<= 1) {
            int y = __shfl_up_sync(0xffffffffu, xx, d);
            if (tid >= d) xx += y;
        }
        wt[tid] = xx - t;   // exclusive warp offsets
    }
    __syncthreads();
    int incl = x + wt[tid >> 5];
    if (i < NN) g_rowptr[i] = incl - v;          // block-local exclusive
    if (tid == 1023) g_blocksum[blockIdx.x] = incl;
    // fused dinv
    if (i < NN) {
        float d = g_deg[i];
        g_deg[i] = (d > 0.f) ? rsqrtf(fmaxf(d, 1e-30f)) : 0.f;
    }
}

// phase B: exclusive scan of NB block sums (1 block, 128 threads)
__global__ void k_scanB() {
    __shared__ int wt[4];
    int tid = threadIdx.x;   // 128
    int v = (tid < NB) ? g_blocksum[tid] : 0;
    int x = v;
    #pragma unroll
    for (int d = 1; d < 32; d <<= 1) {
        int y = __shfl_up_sync(0xffffffffu, x, d);
        if ((tid & 31) >= d) x += y;
    }
    if ((tid & 31) == 31) wt[tid >> 5] = x;
    __syncthreads();
    if (tid < 4) {
        int t = wt[tid];
        int xx = t;
        #pragma unroll
        for (int d = 1; d < 4; d <<= 1) {
            int y = __shfl_up_sync(0x0000000fu, xx, d);
            if (tid >= d) xx += y;
        }
        wt[tid] = xx - t;
    }
    __syncthreads();
    int incl = x + wt[tid >> 5];
    if (tid < NB) g_blockoff[tid] = incl - v;
    if (tid == NB - 1) g_rowptr[NN] = incl;
}

// phase C: add block offsets, write final rowptr + cursor
__global__ void __launch_bounds__(1024) k_scanC() {
    int i = blockIdx.x * 1024 + threadIdx.x;
    if (i >= NN) return;
    int out = g_rowptr[i] + g_blockoff[blockIdx.x];
    g_rowptr[i] = out;
    g_cursor[i] = out;
}

__global__ void k_scatter(const int* __restrict__ ei,
                          const float* __restrict__ ew) {
    int e = blockIdx.x * blockDim.x + threadIdx.x;
    if (e >= EA) return;
    int src, dst; float w;
    if (e < EE) { src = ei[e]; dst = ei[EE + e]; w = ew[e]; }
    else        { src = dst = e - EE;            w = 1.f;   }
    float nv = g_deg[src] * w * g_deg[dst];
    int idx = atomicAdd(&g_cursor[dst], 1);
    g_cv[idx] = make_int2(src, __float_as_int(nv));
}

// ---------------- GEMMs -----------------------------------------------------
// g_bufA[N,32] = X[N,128] @ W[128,32]
__global__ void __launch_bounds__(256) k_gemm128(const float* __restrict__ X,
                                                 const float* __restrict__ W) {
    __shared__ float4 sW[128 * 8];   // W as [k][o/4]
    __shared__ float  sX[256 * 17];  // 16-wide k-chunk, pad 17
    int tid = threadIdx.x;
    for (int i = tid; i < 1024; i += 256) sW[i] = ((const float4*)W)[i];
    float acc[32];
    #pragma unroll
    for (int o = 0; o < 32; o++) acc[o] = 0.f;
    int row = blockIdx.x * 256 + tid;
    for (int kc = 0; kc < 8; kc++) {
        __syncthreads();
        for (int i = tid; i < 256 * 16; i += 256) {
            int r = i >> 4, c = i & 15;
            int rr = blockIdx.x * 256 + r;
            sX[r * 17 + c] = (rr < NN) ? X[rr * 128 + kc * 16 + c] : 0.f;
        }
        __syncthreads();
        #pragma unroll
        for (int kk = 0; kk < 16; kk++) {
            float xv = sX[tid * 17 + kk];
            int k = kc * 16 + kk;
            #pragma unroll
            for (int o4 = 0; o4 < 8; o4++) {
                float4 wv = sW[k * 8 + o4];
                acc[o4 * 4 + 0] += xv * wv.x;
                acc[o4 * 4 + 1] += xv * wv.y;
                acc[o4 * 4 + 2] += xv * wv.z;
                acc[o4 * 4 + 3] += xv * wv.w;
            }
        }
    }
    if (row < NN) {
        float4* Y4 = (float4*)g_bufA;
        #pragma unroll
        for (int j = 0; j < 8; j++)
            Y4[row * 8 + j] = make_float4(acc[4*j], acc[4*j+1], acc[4*j+2], acc[4*j+3]);
    }
}

// g_bufA[N,32] = g_bufB[N,32] @ W[32,32]
__global__ void __launch_bounds__(256) k_gemm32(const float* __restrict__ W) {
    __shared__ float4 sW[32 * 8];
    __shared__ float  sX[256 * 33];
    int tid = threadIdx.x;
    for (int i = tid; i < 256; i += 256) sW[i] = ((const float4*)W)[i];
    for (int i = tid; i < 256 * 32; i += 256) {
        int r = i >> 5, c = i & 31;
        int rr = blockIdx.x * 256 + r;
        sX[r * 33 + c] = (rr < NN) ? g_bufB[rr * 32 + c] : 0.f;
    }
    __syncthreads();
    float acc[32];
    #pragma unroll
    for (int o = 0; o < 32; o++) acc[o] = 0.f;
    #pragma unroll
    for (int kk = 0; kk < 32; kk++) {
        float xv = sX[tid * 33 + kk];
        #pragma unroll
        for (int o4 = 0; o4 < 8; o4++) {
            float4 wv = sW[kk * 8 + o4];
            acc[o4 * 4 + 0] += xv * wv.x;
            acc[o4 * 4 + 1] += xv * wv.y;
            acc[o4 * 4 + 2] += xv * wv.z;
            acc[o4 * 4 + 3] += xv * wv.w;
        }
    }
    int row = blockIdx.x * 256 + tid;
    if (row < NN) {
        float4* Y4 = (float4*)g_bufA;
        #pragma unroll
        for (int j = 0; j < 8; j++)
            Y4[row * 8 + j] = make_float4(acc[4*j], acc[4*j+1], acc[4*j+2], acc[4*j+3]);
    }
}

// ---------------- edge aggregation (gather, warp per node) ------------------
__global__ void __launch_bounds__(256) k_agg(const float* __restrict__ bias, int relu) {
    int w = (blockIdx.x * blockDim.x + threadIdx.x) >> 5;
    int lane = threadIdx.x & 31;
    if (w >= NN) return;
    int beg = g_rowptr[w], end = g_rowptr[w + 1];
    float acc = 0.f;
    #pragma unroll 4
    for (int e = beg; e < end; e++) {
        int2 cv = __ldg(&g_cv[e]);
        acc += __int_as_float(cv.y) * __ldg(&g_bufA[cv.x * 32 + lane]);
    }
    acc += bias[lane];
    if (relu) acc = fmaxf(acc, 0.f);
    g_bufB[w * 32 + lane] = acc;
}

// ---------------- mean pool -------------------------------------------------
__global__ void k_pool(const int* __restrict__ batch) {
    int i = blockIdx.x * blockDim.x + threadIdx.x;
    if (i >= NN * 32) return;
    int n = i >> 5, f = i & 31;
    int b = batch[n];
    atomicAdd(&g_pool[b * 32 + f], g_bufB[i]);
    if (f == 0) atomicAdd(&g_cnt[b], 1);
}

// ---------------- MLP head (single block) -----------------------------------
__global__ void k_mlp(const float* __restrict__ L1w, const float* __restrict__ L1b,
                      const float* __restrict__ L2w, const float* __restrict__ L2b,
                      const float* __restrict__ L3w, const float* __restrict__ L3b,
                      const float* __restrict__ L4w, const float* __restrict__ L4b,
                      float* __restrict__ out) {
    __shared__ float A[GG * MM];
    __shared__ float B[GG * MM];
    int tid = threadIdx.x;  // 256
    for (int i = tid; i < GG * HH; i += 256) {
        int g = i >> 5, f = i & 31;
        float c = (float)g_cnt[g];
        if (c < 1.f) c = 1.f;
        A[g * MM + f] = g_pool[i] / c;
    }
    __syncthreads();
    // L1: 32 -> 64, relu
    for (int i = tid; i < GG * MM; i += 256) {
        int g = i >> 6, m = i & 63;
        float a = L1b[m];
        #pragma unroll
        for (int k = 0; k < HH; k++) a += A[g * MM + k] * L1w[k * MM + m];
        B[g * MM + m] = fmaxf(a, 0.f);
    }
    __syncthreads();
    // L2: 64 -> 64, relu
    for (int i = tid; i < GG * MM; i += 256) {
        int g = i >> 6, m = i & 63;
        float a = L2b[m];
        #pragma unroll
        for (int k = 0; k < MM; k++) a += B[g * MM + k] * L2w[k * MM + m];
        A[g * MM + m] = fmaxf(a, 0.f);
    }
    __syncthreads();
    // L3: 64 -> 64, relu
    for (int i = tid; i < GG * MM; i += 256) {
        int g = i >> 6, m = i & 63;
        float a = L3b[m];
        #pragma unroll
        for (int k = 0; k < MM; k++) a += A[g * MM + k] * L3w[k * MM + m];
        B[g * MM + m] = fmaxf(a, 0.f);
    }
    __syncthreads();
    // L4: 64 -> 10
    for (int i = tid; i < GG * CC; i += 256) {
        int g = i / CC, c = i - g * CC;
        float a = L4b[c];
        #pragma unroll
        for (int k = 0; k < MM; k++) a += B[g * MM + k] * L4w[k * CC + c];
        out[i] = a;
    }
}

// ---------------- launch -----------------------------------------------------
extern "C" void kernel_launch(void* const* d_in, const int* in_sizes, int n_in,
                              void* d_out, int out_size) {
    const float* x    = (const float*)d_in[0];
    const float* ew   = (const float*)d_in[1];
    const float* W1   = (const float*)d_in[2];
    const float* b1   = (const float*)d_in[3];
    const float* W2   = (const float*)d_in[4];
    const float* b2   = (const float*)d_in[5];
    const float* W3   = (const float*)d_in[6];
    const float* b3   = (const float*)d_in[7];
    const float* L1w  = (const float*)d_in[8];
    const float* L1b  = (const float*)d_in[9];
    const float* L2w  = (const float*)d_in[10];
    const float* L2b  = (const float*)d_in[11];
    const float* L3w  = (const float*)d_in[12];
    const float* L3b  = (const float*)d_in[13];
    const float* L4w  = (const float*)d_in[14];
    const float* L4b  = (const float*)d_in[15];
    const int*   ei   = (const int*)d_in[16];   // int32 (JAX x64 disabled)
    const int*   bat  = (const int*)d_in[17];   // int32
    float* out = (float*)d_out;

    const int nb_node  = (NN + 255) / 256;          // 391
    const int nb_edge  = (EA + 255) / 256;          // 12891
    const int nb_nwarp = (NN * 32 + 255) / 256;     // 12500

    k_zero<<<nb_node, 256>>>();
    k_hist<<<nb_edge, 256>>>(ei, ew);
    k_scanA<<<NB, 1024>>>();
    k_scanB<<<1, 128>>>();
    k_scanC<<<NB, 1024>>>();
    k_scatter<<<nb_edge, 256>>>(ei, ew);

    // conv1
    k_gemm128<<<nb_node, 256>>>(x, W1);
    k_agg<<<nb_nwarp, 256>>>(b1, 1);
    // conv2
    k_gemm32<<<nb_node, 256>>>(W2);
    k_agg<<<nb_nwarp, 256>>>(b2, 1);
    // conv3
    k_gemm32<<<nb_node, 256>>>(W3);
    k_agg<<<nb_nwarp, 256>>>(b3, 0);

    k_pool<<<nb_nwarp, 256>>>(bat);
    k_mlp<<<1, 256>>>(L1w, L1b, L2w, L2b, L3w, L3b, L4w, L4b, out);
}